// round 15
// baseline (speedup 1.0000x reference)
#include <cuda_runtime.h>
#include <cuda_fp16.h>
#include <cstdint>

// ---------------- problem constants ----------------
static constexpr int TOKENS = 4096;
static constexpr int IN_F   = 4096;
static constexpr int OUT_F  = 11008;
static constexpr int G      = 704512;   // OUT_F*IN_F/64
static constexpr int RHALF  = 32;       // GS/2
static constexpr int A_DIM  = 172;      // G / IN_F

// ---------------- GEMM tiling ----------------
static constexpr int M_TILE = 128;
static constexpr int N_TILE = 128;
static constexpr int K_TILE = 64;
static constexpr int K_ITERS = IN_F / K_TILE;              // 64
static constexpr int STAGES = 3;
static constexpr int A_TILE_BYTES = M_TILE * K_TILE * 2;   // 16384
static constexpr int B_TILE_BYTES = N_TILE * K_TILE * 2;   // 16384
static constexpr int STAGE_BYTES  = A_TILE_BYTES + B_TILE_BYTES;   // 32768
static constexpr int SMEM_DYN     = STAGES * STAGE_BYTES + 1024;   // 99328 (2 CTAs/SM)

static constexpr int M_TILES = TOKENS / M_TILE;   // 32
static constexpr int N_TILES = OUT_F / N_TILE;    // 86
static constexpr int TOTAL_TILES = M_TILES * N_TILES;   // 2752

static constexpr int NWARPS = 4;                  // 2x2 warp grid, 64x64 warp tiles
static constexpr int KI_PIECE = 16;               // K-iters per split piece (K/4)

// fused prepass block ranges
static constexpr int PREP_X_BLOCKS = (TOKENS * IN_F / 8) / 256;       // 8192
static constexpr int PREP_W_BLOCKS = (G / 8) / 256 * RHALF;           // 344*32 = 11008
static constexpr int PREP_W_XDIM   = (G / 8) / 256;                   // 344

// ---------------- scratch (device globals: allocation-free) ----------------
__device__ __half d_Xt[(size_t)TOKENS * IN_F];
__device__ __half d_Wt[(size_t)OUT_F * IN_F];

// ---------------- small PTX helpers ----------------
__device__ __forceinline__ uint32_t smem_u32(const void* p) {
    uint32_t a;
    asm("{ .reg .u64 t; cvta.to.shared.u64 t, %1; cvt.u32.u64 %0, t; }" : "=r"(a) : "l"(p));
    return a;
}

#define MBARRIER_INIT(addr, cnt) \
    asm volatile("mbarrier.init.shared.b64 [%0], %1;" :: "r"(addr), "r"(cnt) : "memory")
#define MBARRIER_EXPECT_TX(addr, bytes) \
    asm volatile("mbarrier.arrive.expect_tx.shared.b64 _, [%0], %1;" :: "r"(addr), "r"(bytes) : "memory")
#define MBARRIER_ARRIVE(addr) \
    asm volatile("mbarrier.arrive.shared.b64 _, [%0];" :: "r"(addr) : "memory")

__device__ __forceinline__ void mbar_wait(uint32_t mbar, uint32_t parity) {
    uint32_t done = 0;
    while (!done) {
        asm volatile(
            "{\n\t.reg .pred p;\n\t"
            "mbarrier.try_wait.parity.shared::cta.b64 p, [%1], %2;\n\t"
            "selp.b32 %0, 1, 0, p;\n\t}"
            : "=r"(done) : "r"(mbar), "r"(parity) : "memory");
    }
}

// 1-D bulk copy gmem -> smem with mbarrier complete_tx (no tensormap needed)
__device__ __forceinline__ void bulk_g2s(uint32_t dst_smem, const void* src, uint32_t bytes, uint32_t mbar) {
    asm volatile(
        "cp.async.bulk.shared::cluster.global.mbarrier::complete_tx::bytes [%0], [%1], %2, [%3];"
        :: "r"(dst_smem), "l"(src), "r"(bytes), "r"(mbar) : "memory");
}

__device__ __forceinline__ void ldsm4(uint32_t r[4], uint32_t addr) {
    asm volatile("ldmatrix.sync.aligned.m8n8.x4.shared.b16 {%0,%1,%2,%3}, [%4];"
        : "=r"(r[0]), "=r"(r[1]), "=r"(r[2]), "=r"(r[3]) : "r"(addr));
}

__device__ __forceinline__ void mma16816(float c[4], const uint32_t a[4], uint32_t b0, uint32_t b1) {
    asm volatile(
        "mma.sync.aligned.m16n8k16.row.col.f32.f16.f16.f32 "
        "{%0,%1,%2,%3}, {%4,%5,%6,%7}, {%8,%9}, {%0,%1,%2,%3};"
        : "+f"(c[0]), "+f"(c[1]), "+f"(c[2]), "+f"(c[3])
        : "r"(a[0]), "r"(a[1]), "r"(a[2]), "r"(a[3]), "r"(b0), "r"(b1));
}

#define REDADD(p, v) \
    asm volatile("red.global.add.f32 [%0], %1;" :: "l"(p), "f"(v) : "memory")

__device__ __forceinline__ uint32_t sw128(uint32_t off) { return off ^ ((off >> 3) & 0x70); }

union H8 { __half h[8]; uint4 u; };

// ---------------- fused prepass: x-convert + W-dequant + bias-init -----------
__global__ void __launch_bounds__(256)
prep_kernel(const float* __restrict__ x,
            const int* __restrict__ Wq,
            const float* __restrict__ scale,
            const float* __restrict__ zero,
            float* __restrict__ out,
            const float* __restrict__ bias,
            int F) {
    const int bid = blockIdx.x;
    const int tid = threadIdx.x;

    if (bid < PREP_X_BLOCKS) {
        // ---- x fp32 -> fp16, tiled+swizzled ----
        int id = bid * 256 + tid;       // 2,097,152 total
        int t = id >> 9;                // token
        int k = (id & 511) << 3;        // 8 consecutive k
        const float4* xp = reinterpret_cast<const float4*>(x + (size_t)t * IN_F + k);
        float4 x0 = xp[0], x1 = xp[1];
        H8 v;
        v.h[0] = __float2half_rn(x0.x); v.h[1] = __float2half_rn(x0.y);
        v.h[2] = __float2half_rn(x0.z); v.h[3] = __float2half_rn(x0.w);
        v.h[4] = __float2half_rn(x1.x); v.h[5] = __float2half_rn(x1.y);
        v.h[6] = __float2half_rn(x1.z); v.h[7] = __float2half_rn(x1.w);
        int m = t >> 7, rt = t & 127, kt = k >> 6, col = k & 63;
        uint32_t off = sw128((uint32_t)(rt * 128 + col * 2));
        *reinterpret_cast<uint4*>(reinterpret_cast<char*>(d_Xt)
            + (((size_t)(m * 64 + kt)) << 14) + off) = v.u;
    } else if (bid < PREP_X_BLOCKS + PREP_W_BLOCKS) {
        // ---- dequant W_q -> fp16, tiled+swizzled ----
        int idx = bid - PREP_X_BLOCKS;
        int r  = idx / PREP_W_XDIM;                   // 0..31
        int gb = (idx % PREP_W_XDIM) * 256 + tid;     // 0..88063
        int g  = gb << 3;                             // 8 consecutive groups
        const int4* qp = reinterpret_cast<const int4*>(Wq + (size_t)r * G + g);
        int4 q0 = qp[0], q1 = qp[1];
        float4 s0 = *reinterpret_cast<const float4*>(scale + g);
        float4 s1 = *reinterpret_cast<const float4*>(scale + g + 4);
        float4 z0 = *reinterpret_cast<const float4*>(zero + g);
        float4 z1 = *reinterpret_cast<const float4*>(zero + g + 4);

        int v[8] = {q0.x, q0.y, q0.z, q0.w, q1.x, q1.y, q1.z, q1.w};
        float ss[8] = {s0.x, s0.y, s0.z, s0.w, s1.x, s1.y, s1.z, s1.w};
        float zz[8] = {z0.x, z0.y, z0.z, z0.w, z1.x, z1.y, z1.z, z1.w};

        H8 hi, lo;
#pragma unroll
        for (int j = 0; j < 8; j++) {
            float h = (float)((v[j] >> 4) & 0xF);
            float l = (float)(v[j] & 0xF);
            hi.h[j] = __float2half_rn((h - zz[j]) * ss[j]);
            lo.h[j] = __float2half_rn((l - zz[j]) * ss[j]);
        }
        int a = g >> 12, b = g & 4095;
        int o_hi = r * A_DIM + a;
        int o_lo = o_hi + RHALF * A_DIM;   // +5504
        int kt = b >> 6, col = b & 63;
        {
            int n = o_hi >> 7, rt = o_hi & 127;
            uint32_t off = sw128((uint32_t)(rt * 128 + col * 2));
            *reinterpret_cast<uint4*>(reinterpret_cast<char*>(d_Wt)
                + (((size_t)(n * 64 + kt)) << 14) + off) = hi.u;
        }
        {
            int n = o_lo >> 7, rt = o_lo & 127;
            uint32_t off = sw128((uint32_t)(rt * 128 + col * 2));
            *reinterpret_cast<uint4*>(reinterpret_cast<char*>(d_Wt)
                + (((size_t)(n * 64 + kt)) << 14) + off) = lo.u;
        }
    } else {
        // ---- bias-init for K-split tiles (their pieces use red.global.add) ----
        int idx = (bid - PREP_X_BLOCKS - PREP_W_BLOCKS) * 256 + tid;
        int tile = F + (idx >> 12);                 // 4096 float4 per 128x128 tile
        int e = (idx & 4095) << 2;
        int r = e >> 7, c = e & 127;
        int m0 = (tile & 31) * M_TILE, n0 = (tile >> 5) * N_TILE;
        float4 b = *reinterpret_cast<const float4*>(bias + n0 + c);
        *reinterpret_cast<float4*>(out + (size_t)(m0 + r) * OUT_F + n0 + c) = b;
    }
}

// ---------------- kernel 3: HMMA fp16 GEMM + bias ----------------
// Identical to the round-13 winner EXCEPT: the per-iteration refill role
// rotates across warps (warp kt&3 refills), so the producer overhead
// (empty-wait + 2 bulk issues + expect_tx) is spread 1/4 per warp instead of
// always landing on warp 0 (each warp owns one SMSP at 128 threads; a fixed
// producer warp is a systematic straggler that the full-barrier rendezvous
// propagates to the whole CTA).
__global__ void __launch_bounds__(128, 2)
gemm_kernel(float* __restrict__ out, const float* __restrict__ bias, int F) {
    extern __shared__ __align__(1024) char dynsm[];
    __shared__ __align__(8) unsigned long long bars[2 * STAGES];  // full / empty

    const int tid = threadIdx.x;
    const int wid = tid >> 5, lane = tid & 31;
    const int warp_m = wid >> 1;       // 0..1  (64 rows each)
    const int warp_n = wid & 1;        // 0..1  (64 cols each)

    // ---- tile / K-range decode ----
    const int bid = blockIdx.x;
    int tile, k0, ki;
    bool addmode;
    if (bid < F) {
        tile = bid; k0 = 0; ki = K_ITERS; addmode = false;
    } else {
        int idx = bid - F;
        tile = F + (idx >> 2);
        k0 = (idx & 3) * KI_PIECE;
        ki = KI_PIECE;
        addmode = true;
    }
    const int mt = tile & 31;
    const int nt = tile >> 5;

    uint32_t base = (smem_u32(dynsm) + 1023u) & ~1023u;
    uint32_t bar0 = smem_u32(&bars[0]);

    if (tid == 0) {
#pragma unroll
        for (int s = 0; s < STAGES; s++) {
            MBARRIER_INIT(bar0 + 8 * s, 1);                   // full: tx-based
            MBARRIER_INIT(bar0 + 8 * (STAGES + s), NWARPS);   // empty: one arrive per warp
        }
        asm volatile("fence.proxy.async.shared::cta;" ::: "memory");
    }
    __syncthreads();

    const char* gA = reinterpret_cast<const char*>(d_Xt)
                   + ((size_t)(mt * K_ITERS + k0)) * (size_t)A_TILE_BYTES;
    const char* gB = reinterpret_cast<const char*>(d_Wt)
                   + ((size_t)(nt * K_ITERS + k0)) * (size_t)B_TILE_BYTES;

    // prologue: fill all stages
    if (tid == 0) {
#pragma unroll
        for (int j = 0; j < STAGES; j++) {
            uint32_t full = bar0 + 8 * j;
            MBARRIER_EXPECT_TX(full, (uint32_t)STAGE_BYTES);
            bulk_g2s(base + j * STAGE_BYTES,                gA + (size_t)j * A_TILE_BYTES, A_TILE_BYTES, full);
            bulk_g2s(base + j * STAGE_BYTES + A_TILE_BYTES, gB + (size_t)j * B_TILE_BYTES, B_TILE_BYTES, full);
        }
    }

    // per-thread ldmatrix address components (SW128 xor collapses to a constant)
    const int a_row = warp_m * 64 + (lane & 15);
    const uint32_t a_rowoff = (uint32_t)a_row * 128;
    const uint32_t a_xor = (uint32_t)(a_row & 7) << 4;
    const uint32_t a_kc  = (uint32_t)(lane >> 4) << 4;      // 0 or 16 bytes

    const int b_row = warp_n * 64 + ((lane >> 4) << 3) + (lane & 7);
    const uint32_t b_rowoff = (uint32_t)b_row * 128;
    const uint32_t b_xor = (uint32_t)(b_row & 7) << 4;
    const uint32_t b_kc  = (uint32_t)((lane >> 3) & 1) << 4;

    float acc[4][8][4];    // 4 m16 blocks x 8 n8 blocks x 4 regs = 128 regs
#pragma unroll
    for (int i = 0; i < 4; i++)
#pragma unroll
        for (int j = 0; j < 8; j++)
#pragma unroll
            for (int q = 0; q < 4; q++) acc[i][j][q] = 0.0f;

    int s = 0;
    uint32_t phase = 0;
#pragma unroll 1
    for (int kt = 0; kt < ki; kt++) {
        mbar_wait(bar0 + 8 * s, phase);
        uint32_t As = base + s * STAGE_BYTES;
        uint32_t Bs = As + A_TILE_BYTES;
#pragma unroll
        for (int ks = 0; ks < 4; ks++) {
            const uint32_t kb = (uint32_t)ks * 32;
            uint32_t a[4][4];
#pragma unroll
            for (int mb = 0; mb < 4; mb++)
                ldsm4(a[mb], As + a_rowoff + mb * 2048 + ((kb + a_kc) ^ a_xor));
#pragma unroll
            for (int pb = 0; pb < 4; pb++) {
                uint32_t b[4];
                ldsm4(b, Bs + b_rowoff + pb * 2048 + ((kb + b_kc) ^ b_xor));
#pragma unroll
                for (int mb = 0; mb < 4; mb++) {
                    mma16816(acc[mb][2 * pb],     a[mb], b[0], b[1]);
                    mma16816(acc[mb][2 * pb + 1], a[mb], b[2], b[3]);
                }
            }
        }
        // warp done with stage s (ldmatrix is warp-synchronous)
        if (lane == 0) {
            MBARRIER_ARRIVE(bar0 + 8 * (STAGES + s));
            // rotating producer: warp (kt & 3) refills this stage
            if (wid == (kt & 3) && kt + STAGES < ki) {
                mbar_wait(bar0 + 8 * (STAGES + s), phase);
                int j = kt + STAGES;
                uint32_t full = bar0 + 8 * s;
                MBARRIER_EXPECT_TX(full, (uint32_t)STAGE_BYTES);
                bulk_g2s(base + s * STAGE_BYTES,                gA + (size_t)j * A_TILE_BYTES, A_TILE_BYTES, full);
                bulk_g2s(base + s * STAGE_BYTES + A_TILE_BYTES, gB + (size_t)j * B_TILE_BYTES, B_TILE_BYTES, full);
            }
        }
        if (++s == STAGES) { s = 0; phase ^= 1; }
    }

    // ---- epilogue ----
    const int m0 = mt * M_TILE;
    const int n0 = nt * N_TILE;
    const int col = n0 + warp_n * 64 + (lane & 3) * 2;

    if (!addmode) {
        float2 bb[8];
#pragma unroll
        for (int nf = 0; nf < 8; nf++)
            bb[nf] = *reinterpret_cast<const float2*>(bias + col + nf * 8);

#pragma unroll
        for (int mb = 0; mb < 4; mb++) {
            const int r0 = m0 + warp_m * 64 + mb * 16 + (lane >> 2);
            float* p0 = out + (size_t)r0 * OUT_F;
            float* p1 = p0 + (size_t)8 * OUT_F;
#pragma unroll
            for (int nf = 0; nf < 8; nf++) {
                float2 v0, v1;
                v0.x = acc[mb][nf][0] + bb[nf].x;
                v0.y = acc[mb][nf][1] + bb[nf].y;
                v1.x = acc[mb][nf][2] + bb[nf].x;
                v1.y = acc[mb][nf][3] + bb[nf].y;
                *reinterpret_cast<float2*>(p0 + col + nf * 8) = v0;
                *reinterpret_cast<float2*>(p1 + col + nf * 8) = v1;
            }
        }
    } else {
        // K-split piece: accumulate into pre-biased output
#pragma unroll
        for (int mb = 0; mb < 4; mb++) {
            const int r0 = m0 + warp_m * 64 + mb * 16 + (lane >> 2);
            float* p0 = out + (size_t)r0 * OUT_F;
            float* p1 = p0 + (size_t)8 * OUT_F;
#pragma unroll
            for (int nf = 0; nf < 8; nf++) {
                REDADD(p0 + col + nf * 8,     acc[mb][nf][0]);
                REDADD(p0 + col + nf * 8 + 1, acc[mb][nf][1]);
                REDADD(p1 + col + nf * 8,     acc[mb][nf][2]);
                REDADD(p1 + col + nf * 8 + 1, acc[mb][nf][3]);
            }
        }
    }
}

// ---------------- launch ----------------
extern "C" void kernel_launch(void* const* d_in, const int* in_sizes, int n_in,
                              void* d_out, int out_size) {
    const float* x     = (const float*)d_in[0];
    const int*   Wq    = (const int*)  d_in[1];
    const float* scale = (const float*)d_in[2];
    const float* zero  = (const float*)d_in[3];
    const float* bias  = (const float*)d_in[4];
    float* out = (float*)d_out;

    int sm_count = 148;
    cudaDeviceGetAttribute(&sm_count, cudaDevAttrMultiProcessorCount, 0);
    int slots = 2 * sm_count;
    int S = TOTAL_TILES - 9 * slots;     // tiles to K-split (88 on 148 SMs, 16 on 152)
    if (S < 0) S = 0;
    int F = TOTAL_TILES - S;

    prep_kernel<<<PREP_X_BLOCKS + PREP_W_BLOCKS + S * 16, 256>>>(
        x, Wq, scale, zero, out, bias, F);

    cudaFuncSetAttribute(gemm_kernel, cudaFuncAttributeMaxDynamicSharedMemorySize, SMEM_DYN);
    gemm_kernel<<<F + 4 * S, 128, SMEM_DYN>>>(out, bias, F);
}

// round 16
// speedup vs baseline: 1.0313x; 1.0313x over previous
#include <cuda_runtime.h>
#include <cuda_fp16.h>
#include <cstdint>

// ---------------- problem constants ----------------
static constexpr int TOKENS = 4096;
static constexpr int IN_F   = 4096;
static constexpr int OUT_F  = 11008;
static constexpr int G      = 704512;   // OUT_F*IN_F/64
static constexpr int RHALF  = 32;       // GS/2
static constexpr int A_DIM  = 172;      // G / IN_F

// ---------------- GEMM tiling ----------------
static constexpr int M_TILE = 128;
static constexpr int N_TILE = 128;
static constexpr int K_TILE = 64;
static constexpr int K_ITERS = IN_F / K_TILE;              // 64
static constexpr int STAGES = 3;
static constexpr int A_TILE_BYTES = M_TILE * K_TILE * 2;   // 16384
static constexpr int B_TILE_BYTES = N_TILE * K_TILE * 2;   // 16384
static constexpr int STAGE_BYTES  = A_TILE_BYTES + B_TILE_BYTES;   // 32768
static constexpr int SMEM_DYN     = STAGES * STAGE_BYTES + 1024;   // 99328 (2 CTAs/SM)

static constexpr int M_TILES = TOKENS / M_TILE;   // 32
static constexpr int N_TILES = OUT_F / N_TILE;    // 86
static constexpr int TOTAL_TILES = M_TILES * N_TILES;   // 2752

static constexpr int NWARPS = 4;                  // 2x2 warp grid, 64x64 warp tiles
static constexpr int KI_PIECE = 16;               // K-iters per split piece (K/4)

// fused prepass block ranges
static constexpr int PREP_X_BLOCKS = (TOKENS * IN_F / 8) / 256;       // 8192
static constexpr int PREP_W_BLOCKS = (G / 8) / 256 * RHALF;           // 344*32 = 11008
static constexpr int PREP_W_XDIM   = (G / 8) / 256;                   // 344

// ---------------- scratch (device globals: allocation-free) ----------------
__device__ __half d_Xt[(size_t)TOKENS * IN_F];
__device__ __half d_Wt[(size_t)OUT_F * IN_F];

// ---------------- small PTX helpers ----------------
__device__ __forceinline__ uint32_t smem_u32(const void* p) {
    uint32_t a;
    asm("{ .reg .u64 t; cvta.to.shared.u64 t, %1; cvt.u32.u64 %0, t; }" : "=r"(a) : "l"(p));
    return a;
}

#define MBARRIER_INIT(addr, cnt) \
    asm volatile("mbarrier.init.shared.b64 [%0], %1;" :: "r"(addr), "r"(cnt) : "memory")
#define MBARRIER_EXPECT_TX(addr, bytes) \
    asm volatile("mbarrier.arrive.expect_tx.shared.b64 _, [%0], %1;" :: "r"(addr), "r"(bytes) : "memory")
#define MBARRIER_ARRIVE(addr) \
    asm volatile("mbarrier.arrive.shared.b64 _, [%0];" :: "r"(addr) : "memory")

__device__ __forceinline__ void mbar_wait(uint32_t mbar, uint32_t parity) {
    uint32_t done = 0;
    while (!done) {
        asm volatile(
            "{\n\t.reg .pred p;\n\t"
            "mbarrier.try_wait.parity.shared::cta.b64 p, [%1], %2;\n\t"
            "selp.b32 %0, 1, 0, p;\n\t}"
            : "=r"(done) : "r"(mbar), "r"(parity) : "memory");
    }
}

// 1-D bulk copy gmem -> smem with mbarrier complete_tx (no tensormap needed)
__device__ __forceinline__ void bulk_g2s(uint32_t dst_smem, const void* src, uint32_t bytes, uint32_t mbar) {
    asm volatile(
        "cp.async.bulk.shared::cluster.global.mbarrier::complete_tx::bytes [%0], [%1], %2, [%3];"
        :: "r"(dst_smem), "l"(src), "r"(bytes), "r"(mbar) : "memory");
}

__device__ __forceinline__ void ldsm4(uint32_t r[4], uint32_t addr) {
    asm volatile("ldmatrix.sync.aligned.m8n8.x4.shared.b16 {%0,%1,%2,%3}, [%4];"
        : "=r"(r[0]), "=r"(r[1]), "=r"(r[2]), "=r"(r[3]) : "r"(addr));
}

__device__ __forceinline__ void mma16816(float c[4], const uint32_t a[4], uint32_t b0, uint32_t b1) {
    asm volatile(
        "mma.sync.aligned.m16n8k16.row.col.f32.f16.f16.f32 "
        "{%0,%1,%2,%3}, {%4,%5,%6,%7}, {%8,%9}, {%0,%1,%2,%3};"
        : "+f"(c[0]), "+f"(c[1]), "+f"(c[2]), "+f"(c[3])
        : "r"(a[0]), "r"(a[1]), "r"(a[2]), "r"(a[3]), "r"(b0), "r"(b1));
}

#define REDADD(p, v) \
    asm volatile("red.global.add.f32 [%0], %1;" :: "l"(p), "f"(v) : "memory")

__device__ __forceinline__ uint32_t sw128(uint32_t off) { return off ^ ((off >> 3) & 0x70); }

union H8 { __half h[8]; uint4 u; };

// ---------------- fused prepass: x-convert + W-dequant + bias-init -----------
__global__ void __launch_bounds__(256)
prep_kernel(const float* __restrict__ x,
            const int* __restrict__ Wq,
            const float* __restrict__ scale,
            const float* __restrict__ zero,
            float* __restrict__ out,
            const float* __restrict__ bias,
            int F) {
    const int bid = blockIdx.x;
    const int tid = threadIdx.x;

    if (bid < PREP_X_BLOCKS) {
        // ---- x fp32 -> fp16, tiled+swizzled ----
        int id = bid * 256 + tid;       // 2,097,152 total
        int t = id >> 9;                // token
        int k = (id & 511) << 3;        // 8 consecutive k
        const float4* xp = reinterpret_cast<const float4*>(x + (size_t)t * IN_F + k);
        float4 x0 = xp[0], x1 = xp[1];
        H8 v;
        v.h[0] = __float2half_rn(x0.x); v.h[1] = __float2half_rn(x0.y);
        v.h[2] = __float2half_rn(x0.z); v.h[3] = __float2half_rn(x0.w);
        v.h[4] = __float2half_rn(x1.x); v.h[5] = __float2half_rn(x1.y);
        v.h[6] = __float2half_rn(x1.z); v.h[7] = __float2half_rn(x1.w);
        int m = t >> 7, rt = t & 127, kt = k >> 6, col = k & 63;
        uint32_t off = sw128((uint32_t)(rt * 128 + col * 2));
        *reinterpret_cast<uint4*>(reinterpret_cast<char*>(d_Xt)
            + (((size_t)(m * 64 + kt)) << 14) + off) = v.u;
    } else if (bid < PREP_X_BLOCKS + PREP_W_BLOCKS) {
        // ---- dequant W_q -> fp16, tiled+swizzled ----
        int idx = bid - PREP_X_BLOCKS;
        int r  = idx / PREP_W_XDIM;                   // 0..31
        int gb = (idx % PREP_W_XDIM) * 256 + tid;     // 0..88063
        int g  = gb << 3;                             // 8 consecutive groups
        const int4* qp = reinterpret_cast<const int4*>(Wq + (size_t)r * G + g);
        int4 q0 = qp[0], q1 = qp[1];
        float4 s0 = *reinterpret_cast<const float4*>(scale + g);
        float4 s1 = *reinterpret_cast<const float4*>(scale + g + 4);
        float4 z0 = *reinterpret_cast<const float4*>(zero + g);
        float4 z1 = *reinterpret_cast<const float4*>(zero + g + 4);

        int v[8] = {q0.x, q0.y, q0.z, q0.w, q1.x, q1.y, q1.z, q1.w};
        float ss[8] = {s0.x, s0.y, s0.z, s0.w, s1.x, s1.y, s1.z, s1.w};
        float zz[8] = {z0.x, z0.y, z0.z, z0.w, z1.x, z1.y, z1.z, z1.w};

        H8 hi, lo;
#pragma unroll
        for (int j = 0; j < 8; j++) {
            float h = (float)((v[j] >> 4) & 0xF);
            float l = (float)(v[j] & 0xF);
            hi.h[j] = __float2half_rn((h - zz[j]) * ss[j]);
            lo.h[j] = __float2half_rn((l - zz[j]) * ss[j]);
        }
        int a = g >> 12, b = g & 4095;
        int o_hi = r * A_DIM + a;
        int o_lo = o_hi + RHALF * A_DIM;   // +5504
        int kt = b >> 6, col = b & 63;
        {
            int n = o_hi >> 7, rt = o_hi & 127;
            uint32_t off = sw128((uint32_t)(rt * 128 + col * 2));
            *reinterpret_cast<uint4*>(reinterpret_cast<char*>(d_Wt)
                + (((size_t)(n * 64 + kt)) << 14) + off) = hi.u;
        }
        {
            int n = o_lo >> 7, rt = o_lo & 127;
            uint32_t off = sw128((uint32_t)(rt * 128 + col * 2));
            *reinterpret_cast<uint4*>(reinterpret_cast<char*>(d_Wt)
                + (((size_t)(n * 64 + kt)) << 14) + off) = lo.u;
        }
    } else {
        // ---- bias-init for K-split tiles (their pieces use red.global.add) ----
        int idx = (bid - PREP_X_BLOCKS - PREP_W_BLOCKS) * 256 + tid;
        int tile = F + (idx >> 12);                 // 4096 float4 per 128x128 tile
        int e = (idx & 4095) << 2;
        int r = e >> 7, c = e & 127;
        int m0 = (tile & 31) * M_TILE, n0 = (tile >> 5) * N_TILE;
        float4 b = *reinterpret_cast<const float4*>(bias + n0 + c);
        *reinterpret_cast<float4*>(out + (size_t)(m0 + r) * OUT_F + n0 + c) = b;
    }
}

// ---------------- kernel 3: HMMA fp16 GEMM + bias ----------------
// Round-13 winner with ONE change: the tid-0 refill of a consumed stage is
// DEFERRED by one iteration. tid 0 records (stage, j) after arriving, and
// issues the refill at the top of the NEXT iteration — by which time the other
// warps have had a full extra iteration to arrive on the empty barrier, so the
// producer's rendezvous stall collapses to a poll. With 3 stages the refill is
// still issued 2 iterations before its consumer needs it (ample slack).
__global__ void __launch_bounds__(128, 2)
gemm_kernel(float* __restrict__ out, const float* __restrict__ bias, int F) {
    extern __shared__ __align__(1024) char dynsm[];
    __shared__ __align__(8) unsigned long long bars[2 * STAGES];  // full / empty

    const int tid = threadIdx.x;
    const int wid = tid >> 5, lane = tid & 31;
    const int warp_m = wid >> 1;       // 0..1  (64 rows each)
    const int warp_n = wid & 1;        // 0..1  (64 cols each)

    // ---- tile / K-range decode ----
    const int bid = blockIdx.x;
    int tile, k0, ki;
    bool addmode;
    if (bid < F) {
        tile = bid; k0 = 0; ki = K_ITERS; addmode = false;
    } else {
        int idx = bid - F;
        tile = F + (idx >> 2);
        k0 = (idx & 3) * KI_PIECE;
        ki = KI_PIECE;
        addmode = true;
    }
    const int mt = tile & 31;
    const int nt = tile >> 5;

    uint32_t base = (smem_u32(dynsm) + 1023u) & ~1023u;
    uint32_t bar0 = smem_u32(&bars[0]);

    if (tid == 0) {
#pragma unroll
        for (int s = 0; s < STAGES; s++) {
            MBARRIER_INIT(bar0 + 8 * s, 1);                   // full: tx-based
            MBARRIER_INIT(bar0 + 8 * (STAGES + s), NWARPS);   // empty: one arrive per warp
        }
        asm volatile("fence.proxy.async.shared::cta;" ::: "memory");
    }
    __syncthreads();

    const char* gA = reinterpret_cast<const char*>(d_Xt)
                   + ((size_t)(mt * K_ITERS + k0)) * (size_t)A_TILE_BYTES;
    const char* gB = reinterpret_cast<const char*>(d_Wt)
                   + ((size_t)(nt * K_ITERS + k0)) * (size_t)B_TILE_BYTES;

    // prologue: fill all stages
    if (tid == 0) {
#pragma unroll
        for (int j = 0; j < STAGES; j++) {
            uint32_t full = bar0 + 8 * j;
            MBARRIER_EXPECT_TX(full, (uint32_t)STAGE_BYTES);
            bulk_g2s(base + j * STAGE_BYTES,                gA + (size_t)j * A_TILE_BYTES, A_TILE_BYTES, full);
            bulk_g2s(base + j * STAGE_BYTES + A_TILE_BYTES, gB + (size_t)j * B_TILE_BYTES, B_TILE_BYTES, full);
        }
    }

    // per-thread ldmatrix address components (SW128 xor collapses to a constant)
    const int a_row = warp_m * 64 + (lane & 15);
    const uint32_t a_rowoff = (uint32_t)a_row * 128;
    const uint32_t a_xor = (uint32_t)(a_row & 7) << 4;
    const uint32_t a_kc  = (uint32_t)(lane >> 4) << 4;      // 0 or 16 bytes

    const int b_row = warp_n * 64 + ((lane >> 4) << 3) + (lane & 7);
    const uint32_t b_rowoff = (uint32_t)b_row * 128;
    const uint32_t b_xor = (uint32_t)(b_row & 7) << 4;
    const uint32_t b_kc  = (uint32_t)((lane >> 3) & 1) << 4;

    float acc[4][8][4];    // 4 m16 blocks x 8 n8 blocks x 4 regs = 128 regs
#pragma unroll
    for (int i = 0; i < 4; i++)
#pragma unroll
        for (int j = 0; j < 8; j++)
#pragma unroll
            for (int q = 0; q < 4; q++) acc[i][j][q] = 0.0f;

    int s = 0;
    uint32_t phase = 0;
    // deferred-refill state (tid 0 only)
    int pend_s = -1;
    int pend_j = 0;
    uint32_t pend_ph = 0;

#pragma unroll 1
    for (int kt = 0; kt < ki; kt++) {
        mbar_wait(bar0 + 8 * s, phase);
        // tid 0: perform the refill recorded LAST iteration (empty barrier has
        // had a full extra iteration to flip -> near-zero stall here)
        if (tid == 0 && pend_s >= 0) {
            mbar_wait(bar0 + 8 * (STAGES + pend_s), pend_ph);
            uint32_t full = bar0 + 8 * pend_s;
            MBARRIER_EXPECT_TX(full, (uint32_t)STAGE_BYTES);
            bulk_g2s(base + pend_s * STAGE_BYTES,                gA + (size_t)pend_j * A_TILE_BYTES, A_TILE_BYTES, full);
            bulk_g2s(base + pend_s * STAGE_BYTES + A_TILE_BYTES, gB + (size_t)pend_j * B_TILE_BYTES, B_TILE_BYTES, full);
            pend_s = -1;
        }
        uint32_t As = base + s * STAGE_BYTES;
        uint32_t Bs = As + A_TILE_BYTES;
#pragma unroll
        for (int ks = 0; ks < 4; ks++) {
            const uint32_t kb = (uint32_t)ks * 32;
            uint32_t a[4][4];
#pragma unroll
            for (int mb = 0; mb < 4; mb++)
                ldsm4(a[mb], As + a_rowoff + mb * 2048 + ((kb + a_kc) ^ a_xor));
#pragma unroll
            for (int pb = 0; pb < 4; pb++) {
                uint32_t b[4];
                ldsm4(b, Bs + b_rowoff + pb * 2048 + ((kb + b_kc) ^ b_xor));
#pragma unroll
                for (int mb = 0; mb < 4; mb++) {
                    mma16816(acc[mb][2 * pb],     a[mb], b[0], b[1]);
                    mma16816(acc[mb][2 * pb + 1], a[mb], b[2], b[3]);
                }
            }
        }
        // warp done with stage s (ldmatrix is warp-synchronous)
        if (lane == 0) MBARRIER_ARRIVE(bar0 + 8 * (STAGES + s));
        // tid 0: record the refill for NEXT iteration instead of doing it now
        if (tid == 0 && kt + STAGES < ki) {
            pend_s = s;
            pend_j = kt + STAGES;
            pend_ph = phase;
        }
        if (++s == STAGES) { s = 0; phase ^= 1; }
    }

    // ---- epilogue ----
    const int m0 = mt * M_TILE;
    const int n0 = nt * N_TILE;
    const int col = n0 + warp_n * 64 + (lane & 3) * 2;

    if (!addmode) {
        float2 bb[8];
#pragma unroll
        for (int nf = 0; nf < 8; nf++)
            bb[nf] = *reinterpret_cast<const float2*>(bias + col + nf * 8);

#pragma unroll
        for (int mb = 0; mb < 4; mb++) {
            const int r0 = m0 + warp_m * 64 + mb * 16 + (lane >> 2);
            float* p0 = out + (size_t)r0 * OUT_F;
            float* p1 = p0 + (size_t)8 * OUT_F;
#pragma unroll
            for (int nf = 0; nf < 8; nf++) {
                float2 v0, v1;
                v0.x = acc[mb][nf][0] + bb[nf].x;
                v0.y = acc[mb][nf][1] + bb[nf].y;
                v1.x = acc[mb][nf][2] + bb[nf].x;
                v1.y = acc[mb][nf][3] + bb[nf].y;
                *reinterpret_cast<float2*>(p0 + col + nf * 8) = v0;
                *reinterpret_cast<float2*>(p1 + col + nf * 8) = v1;
            }
        }
    } else {
        // K-split piece: accumulate into pre-biased output
#pragma unroll
        for (int mb = 0; mb < 4; mb++) {
            const int r0 = m0 + warp_m * 64 + mb * 16 + (lane >> 2);
            float* p0 = out + (size_t)r0 * OUT_F;
            float* p1 = p0 + (size_t)8 * OUT_F;
#pragma unroll
            for (int nf = 0; nf < 8; nf++) {
                REDADD(p0 + col + nf * 8,     acc[mb][nf][0]);
                REDADD(p0 + col + nf * 8 + 1, acc[mb][nf][1]);
                REDADD(p1 + col + nf * 8,     acc[mb][nf][2]);
                REDADD(p1 + col + nf * 8 + 1, acc[mb][nf][3]);
            }
        }
    }
}

// ---------------- launch ----------------
extern "C" void kernel_launch(void* const* d_in, const int* in_sizes, int n_in,
                              void* d_out, int out_size) {
    const float* x     = (const float*)d_in[0];
    const int*   Wq    = (const int*)  d_in[1];
    const float* scale = (const float*)d_in[2];
    const float* zero  = (const float*)d_in[3];
    const float* bias  = (const float*)d_in[4];
    float* out = (float*)d_out;

    int sm_count = 148;
    cudaDeviceGetAttribute(&sm_count, cudaDevAttrMultiProcessorCount, 0);
    int slots = 2 * sm_count;
    int S = TOTAL_TILES - 9 * slots;     // tiles to K-split (88 on 148 SMs, 16 on 152)
    if (S < 0) S = 0;
    int F = TOTAL_TILES - S;

    prep_kernel<<<PREP_X_BLOCKS + PREP_W_BLOCKS + S * 16, 256>>>(
        x, Wq, scale, zero, out, bias, F);

    cudaFuncSetAttribute(gemm_kernel, cudaFuncAttributeMaxDynamicSharedMemorySize, SMEM_DYN);
    gemm_kernel<<<F + 4 * S, 128, SMEM_DYN>>>(out, bias, F);
}

// round 17
// speedup vs baseline: 1.0316x; 1.0002x over previous
#include <cuda_runtime.h>
#include <cuda_fp16.h>
#include <cstdint>

// ---------------- problem constants ----------------
static constexpr int TOKENS = 4096;
static constexpr int IN_F   = 4096;
static constexpr int OUT_F  = 11008;
static constexpr int G      = 704512;   // OUT_F*IN_F/64
static constexpr int RHALF  = 32;       // GS/2
static constexpr int A_DIM  = 172;      // G / IN_F

// ---------------- GEMM tiling ----------------
static constexpr int M_TILE = 128;
static constexpr int N_TILE = 128;
static constexpr int K_TILE = 64;
static constexpr int K_ITERS = IN_F / K_TILE;              // 64
static constexpr int STAGES = 3;
static constexpr int A_TILE_BYTES = M_TILE * K_TILE * 2;   // 16384
static constexpr int B_TILE_BYTES = N_TILE * K_TILE * 2;   // 16384
static constexpr int STAGE_BYTES  = A_TILE_BYTES + B_TILE_BYTES;   // 32768
static constexpr int SMEM_DYN     = STAGES * STAGE_BYTES + 1024;   // 99328 (2 CTAs/SM)

static constexpr int M_TILES = TOKENS / M_TILE;   // 32
static constexpr int N_TILES = OUT_F / N_TILE;    // 86
static constexpr int TOTAL_TILES = M_TILES * N_TILES;   // 2752

static constexpr int NWARPS = 4;                  // 2x2 warp grid, 64x64 warp tiles
static constexpr int KI_PIECE = 16;               // K-iters per split piece (K/4)
static constexpr int FULL_PER_CTA = 9;            // full tiles per persistent CTA

// fused prepass block ranges
static constexpr int PREP_X_BLOCKS = (TOKENS * IN_F / 8) / 256;       // 8192
static constexpr int PREP_W_BLOCKS = (G / 8) / 256 * RHALF;           // 344*32 = 11008
static constexpr int PREP_W_XDIM   = (G / 8) / 256;                   // 344

// ---------------- scratch (device globals: allocation-free) ----------------
__device__ __half d_Xt[(size_t)TOKENS * IN_F];
__device__ __half d_Wt[(size_t)OUT_F * IN_F];

// ---------------- small PTX helpers ----------------
__device__ __forceinline__ uint32_t smem_u32(const void* p) {
    uint32_t a;
    asm("{ .reg .u64 t; cvta.to.shared.u64 t, %1; cvt.u32.u64 %0, t; }" : "=r"(a) : "l"(p));
    return a;
}

#define MBARRIER_INIT(addr, cnt) \
    asm volatile("mbarrier.init.shared.b64 [%0], %1;" :: "r"(addr), "r"(cnt) : "memory")
#define MBARRIER_EXPECT_TX(addr, bytes) \
    asm volatile("mbarrier.arrive.expect_tx.shared.b64 _, [%0], %1;" :: "r"(addr), "r"(bytes) : "memory")
#define MBARRIER_ARRIVE(addr) \
    asm volatile("mbarrier.arrive.shared.b64 _, [%0];" :: "r"(addr) : "memory")

__device__ __forceinline__ void mbar_wait(uint32_t mbar, uint32_t parity) {
    uint32_t done = 0;
    while (!done) {
        asm volatile(
            "{\n\t.reg .pred p;\n\t"
            "mbarrier.try_wait.parity.shared::cta.b64 p, [%1], %2;\n\t"
            "selp.b32 %0, 1, 0, p;\n\t}"
            : "=r"(done) : "r"(mbar), "r"(parity) : "memory");
    }
}

// 1-D bulk copy gmem -> smem with mbarrier complete_tx (no tensormap needed)
__device__ __forceinline__ void bulk_g2s(uint32_t dst_smem, const void* src, uint32_t bytes, uint32_t mbar) {
    asm volatile(
        "cp.async.bulk.shared::cluster.global.mbarrier::complete_tx::bytes [%0], [%1], %2, [%3];"
        :: "r"(dst_smem), "l"(src), "r"(bytes), "r"(mbar) : "memory");
}

__device__ __forceinline__ void ldsm4(uint32_t r[4], uint32_t addr) {
    asm volatile("ldmatrix.sync.aligned.m8n8.x4.shared.b16 {%0,%1,%2,%3}, [%4];"
        : "=r"(r[0]), "=r"(r[1]), "=r"(r[2]), "=r"(r[3]) : "r"(addr));
}

__device__ __forceinline__ void mma16816(float c[4], const uint32_t a[4], uint32_t b0, uint32_t b1) {
    asm volatile(
        "mma.sync.aligned.m16n8k16.row.col.f32.f16.f16.f32 "
        "{%0,%1,%2,%3}, {%4,%5,%6,%7}, {%8,%9}, {%0,%1,%2,%3};"
        : "+f"(c[0]), "+f"(c[1]), "+f"(c[2]), "+f"(c[3])
        : "r"(a[0]), "r"(a[1]), "r"(a[2]), "r"(a[3]), "r"(b0), "r"(b1));
}

#define REDADD(p, v) \
    asm volatile("red.global.add.f32 [%0], %1;" :: "l"(p), "f"(v) : "memory")

__device__ __forceinline__ uint32_t sw128(uint32_t off) { return off ^ ((off >> 3) & 0x70); }

union H8 { __half h[8]; uint4 u; };

// ---------------- fused prepass: x-convert + W-dequant + bias-init -----------
__global__ void __launch_bounds__(256)
prep_kernel(const float* __restrict__ x,
            const int* __restrict__ Wq,
            const float* __restrict__ scale,
            const float* __restrict__ zero,
            float* __restrict__ out,
            const float* __restrict__ bias,
            int F) {
    const int bid = blockIdx.x;
    const int tid = threadIdx.x;

    if (bid < PREP_X_BLOCKS) {
        // ---- x fp32 -> fp16, tiled+swizzled ----
        int id = bid * 256 + tid;       // 2,097,152 total
        int t = id >> 9;                // token
        int k = (id & 511) << 3;        // 8 consecutive k
        const float4* xp = reinterpret_cast<const float4*>(x + (size_t)t * IN_F + k);
        float4 x0 = xp[0], x1 = xp[1];
        H8 v;
        v.h[0] = __float2half_rn(x0.x); v.h[1] = __float2half_rn(x0.y);
        v.h[2] = __float2half_rn(x0.z); v.h[3] = __float2half_rn(x0.w);
        v.h[4] = __float2half_rn(x1.x); v.h[5] = __float2half_rn(x1.y);
        v.h[6] = __float2half_rn(x1.z); v.h[7] = __float2half_rn(x1.w);
        int m = t >> 7, rt = t & 127, kt = k >> 6, col = k & 63;
        uint32_t off = sw128((uint32_t)(rt * 128 + col * 2));
        *reinterpret_cast<uint4*>(reinterpret_cast<char*>(d_Xt)
            + (((size_t)(m * 64 + kt)) << 14) + off) = v.u;
    } else if (bid < PREP_X_BLOCKS + PREP_W_BLOCKS) {
        // ---- dequant W_q -> fp16, tiled+swizzled ----
        int idx = bid - PREP_X_BLOCKS;
        int r  = idx / PREP_W_XDIM;                   // 0..31
        int gb = (idx % PREP_W_XDIM) * 256 + tid;     // 0..88063
        int g  = gb << 3;                             // 8 consecutive groups
        const int4* qp = reinterpret_cast<const int4*>(Wq + (size_t)r * G + g);
        int4 q0 = qp[0], q1 = qp[1];
        float4 s0 = *reinterpret_cast<const float4*>(scale + g);
        float4 s1 = *reinterpret_cast<const float4*>(scale + g + 4);
        float4 z0 = *reinterpret_cast<const float4*>(zero + g);
        float4 z1 = *reinterpret_cast<const float4*>(zero + g + 4);

        int v[8] = {q0.x, q0.y, q0.z, q0.w, q1.x, q1.y, q1.z, q1.w};
        float ss[8] = {s0.x, s0.y, s0.z, s0.w, s1.x, s1.y, s1.z, s1.w};
        float zz[8] = {z0.x, z0.y, z0.z, z0.w, z1.x, z1.y, z1.z, z1.w};

        H8 hi, lo;
#pragma unroll
        for (int j = 0; j < 8; j++) {
            float h = (float)((v[j] >> 4) & 0xF);
            float l = (float)(v[j] & 0xF);
            hi.h[j] = __float2half_rn((h - zz[j]) * ss[j]);
            lo.h[j] = __float2half_rn((l - zz[j]) * ss[j]);
        }
        int a = g >> 12, b = g & 4095;
        int o_hi = r * A_DIM + a;
        int o_lo = o_hi + RHALF * A_DIM;   // +5504
        int kt = b >> 6, col = b & 63;
        {
            int n = o_hi >> 7, rt = o_hi & 127;
            uint32_t off = sw128((uint32_t)(rt * 128 + col * 2));
            *reinterpret_cast<uint4*>(reinterpret_cast<char*>(d_Wt)
                + (((size_t)(n * 64 + kt)) << 14) + off) = hi.u;
        }
        {
            int n = o_lo >> 7, rt = o_lo & 127;
            uint32_t off = sw128((uint32_t)(rt * 128 + col * 2));
            *reinterpret_cast<uint4*>(reinterpret_cast<char*>(d_Wt)
                + (((size_t)(n * 64 + kt)) << 14) + off) = lo.u;
        }
    } else {
        // ---- bias-init for K-split tiles (their pieces use red.global.add) ----
        int idx = (bid - PREP_X_BLOCKS - PREP_W_BLOCKS) * 256 + tid;
        int tile = F + (idx >> 12);                 // 4096 float4 per 128x128 tile
        int e = (idx & 4095) << 2;
        int r = e >> 7, c = e & 127;
        int m0 = (tile & 31) * M_TILE, n0 = (tile >> 5) * N_TILE;
        float4 b = *reinterpret_cast<const float4*>(bias + n0 + c);
        *reinterpret_cast<float4*>(out + (size_t)(m0 + r) * OUT_F + n0 + c) = b;
    }
}

// decode work item w for persistent CTA c: 9 full tiles then K-quarter pieces
__device__ __forceinline__ void get_work(int c, int nctas, int F, int w,
                                         const char*& gA, const char*& gB,
                                         int& ki, int& tile, bool& addmode) {
    int k0;
    if (w < FULL_PER_CTA) {
        tile = c + w * nctas; k0 = 0; ki = K_ITERS; addmode = false;
    } else {
        int p = c + (w - FULL_PER_CTA) * nctas;
        tile = F + (p >> 2); k0 = (p & 3) * KI_PIECE; ki = KI_PIECE; addmode = true;
    }
    int mt = tile & 31, nt = tile >> 5;
    gA = reinterpret_cast<const char*>(d_Xt) + ((size_t)(mt * K_ITERS + k0)) * (size_t)A_TILE_BYTES;
    gB = reinterpret_cast<const char*>(d_Wt) + ((size_t)(nt * K_ITERS + k0)) * (size_t)B_TILE_BYTES;
}

// ---------------- kernel 3: persistent HMMA fp16 GEMM + bias ----------------
// Static persistent schedule: grid = 2 CTAs/SM; CTA c owns full tiles
// c, c+n, ... (exactly 9 since F = 9n) then pieces p = c, c+n, ... (<4S).
// No atomics, no tile handoff: every thread derives its work list. The
// 3-stage pipeline NEVER drains: the tid-0 fill cursor streams chunks flat
// across work boundaries with the round-16 deferred-refill mechanics, so
// epilogues overlap prefetched next-tile data and the cold fill happens once
// per CTA instead of once per tile.
__global__ void __launch_bounds__(128, 2)
gemm_kernel(float* __restrict__ out, const float* __restrict__ bias,
            int F, int nctas, int S4) {
    extern __shared__ __align__(1024) char dynsm[];
    __shared__ __align__(8) unsigned long long bars[2 * STAGES];  // full / empty

    const int tid = threadIdx.x;
    const int wid = tid >> 5, lane = tid & 31;
    const int warp_m = wid >> 1;       // 0..1  (64 rows each)
    const int warp_n = wid & 1;        // 0..1  (64 cols each)
    const int c = blockIdx.x;

    int nworks = FULL_PER_CTA;
    for (int p = c; p < S4; p += nctas) nworks++;

    uint32_t base = (smem_u32(dynsm) + 1023u) & ~1023u;
    uint32_t bar0 = smem_u32(&bars[0]);

    if (tid == 0) {
#pragma unroll
        for (int s = 0; s < STAGES; s++) {
            MBARRIER_INIT(bar0 + 8 * s, 1);                   // full: tx-based
            MBARRIER_INIT(bar0 + 8 * (STAGES + s), NWARPS);   // empty: one arrive per warp
        }
        asm volatile("fence.proxy.async.shared::cta;" ::: "memory");
    }
    __syncthreads();

    // ---- producer fill cursor (tid 0 only) ----
    int fw = 0, fkt = 0, f_ki = K_ITERS;
    const char *f_gA = nullptr, *f_gB = nullptr;
    bool f_more = true;
    if (tid == 0) {
        int tl; bool am;
        get_work(c, nctas, F, 0, f_gA, f_gB, f_ki, tl, am);
        // prologue: fill stages 0..2 from the flat chunk sequence
#pragma unroll
        for (int j = 0; j < STAGES; j++) {
            uint32_t full = bar0 + 8 * j;
            MBARRIER_EXPECT_TX(full, (uint32_t)STAGE_BYTES);
            bulk_g2s(base + j * STAGE_BYTES,                f_gA + (size_t)fkt * A_TILE_BYTES, A_TILE_BYTES, full);
            bulk_g2s(base + j * STAGE_BYTES + A_TILE_BYTES, f_gB + (size_t)fkt * B_TILE_BYTES, B_TILE_BYTES, full);
            if (++fkt == f_ki) {
                fkt = 0;
                if (++fw < nworks) get_work(c, nctas, F, fw, f_gA, f_gB, f_ki, tl, am);
                else f_more = false;
            }
        }
    }

    // per-thread ldmatrix address components (SW128 xor collapses to a constant)
    const int a_row = warp_m * 64 + (lane & 15);
    const uint32_t a_rowoff = (uint32_t)a_row * 128;
    const uint32_t a_xor = (uint32_t)(a_row & 7) << 4;
    const uint32_t a_kc  = (uint32_t)(lane >> 4) << 4;      // 0 or 16 bytes

    const int b_row = warp_n * 64 + ((lane >> 4) << 3) + (lane & 7);
    const uint32_t b_rowoff = (uint32_t)b_row * 128;
    const uint32_t b_xor = (uint32_t)(b_row & 7) << 4;
    const uint32_t b_kc  = (uint32_t)((lane >> 3) & 1) << 4;

    float acc[4][8][4];    // 4 m16 blocks x 8 n8 blocks x 4 regs = 128 regs
#pragma unroll
    for (int i = 0; i < 4; i++)
#pragma unroll
        for (int j = 0; j < 8; j++)
#pragma unroll
            for (int q = 0; q < 4; q++) acc[i][j][q] = 0.0f;

    int s = 0;
    uint32_t phase = 0;
    // deferred refill (tid 0 only)
    bool pend = false;
    int pend_s = 0;
    uint32_t pend_ph = 0;
    const char *pA = nullptr, *pB = nullptr;

#pragma unroll 1
    for (int w = 0; w < nworks; w++) {
        const char *gA_, *gB_;
        int ki, tile; bool addmode;
        get_work(c, nctas, F, w, gA_, gB_, ki, tile, addmode);

#pragma unroll 1
        for (int kt = 0; kt < ki; kt++) {
            mbar_wait(bar0 + 8 * s, phase);
            // tid 0: perform the refill recorded LAST chunk (empty barrier has
            // had a full extra chunk to flip -> near-zero stall here)
            if (tid == 0 && pend) {
                mbar_wait(bar0 + 8 * (STAGES + pend_s), pend_ph);
                uint32_t full = bar0 + 8 * pend_s;
                MBARRIER_EXPECT_TX(full, (uint32_t)STAGE_BYTES);
                bulk_g2s(base + pend_s * STAGE_BYTES,                pA, A_TILE_BYTES, full);
                bulk_g2s(base + pend_s * STAGE_BYTES + A_TILE_BYTES, pB, B_TILE_BYTES, full);
                pend = false;
            }
            uint32_t As = base + s * STAGE_BYTES;
            uint32_t Bs = As + A_TILE_BYTES;
#pragma unroll
            for (int ks = 0; ks < 4; ks++) {
                const uint32_t kb = (uint32_t)ks * 32;
                uint32_t a[4][4];
#pragma unroll
                for (int mb = 0; mb < 4; mb++)
                    ldsm4(a[mb], As + a_rowoff + mb * 2048 + ((kb + a_kc) ^ a_xor));
#pragma unroll
                for (int pb = 0; pb < 4; pb++) {
                    uint32_t b[4];
                    ldsm4(b, Bs + b_rowoff + pb * 2048 + ((kb + b_kc) ^ b_xor));
#pragma unroll
                    for (int mb = 0; mb < 4; mb++) {
                        mma16816(acc[mb][2 * pb],     a[mb], b[0], b[1]);
                        mma16816(acc[mb][2 * pb + 1], a[mb], b[2], b[3]);
                    }
                }
            }
            // warp done with stage s (ldmatrix is warp-synchronous)
            if (lane == 0) MBARRIER_ARRIVE(bar0 + 8 * (STAGES + s));
            // tid 0: record next flat-sequence fill for this freed stage
            if (tid == 0 && f_more) {
                pA = f_gA + (size_t)fkt * A_TILE_BYTES;
                pB = f_gB + (size_t)fkt * B_TILE_BYTES;
                pend_s = s;
                pend_ph = phase;
                pend = true;
                if (++fkt == f_ki) {
                    fkt = 0;
                    if (++fw < nworks) {
                        int tl; bool am;
                        get_work(c, nctas, F, fw, f_gA, f_gB, f_ki, tl, am);
                    } else f_more = false;
                }
            }
            if (++s == STAGES) { s = 0; phase ^= 1; }
        }

        // ---- epilogue for this work item ----
        const int m0 = (tile & 31) * M_TILE;
        const int n0 = (tile >> 5) * N_TILE;
        const int col = n0 + warp_n * 64 + (lane & 3) * 2;

        if (!addmode) {
            float2 bb[8];
#pragma unroll
            for (int nf = 0; nf < 8; nf++)
                bb[nf] = *reinterpret_cast<const float2*>(bias + col + nf * 8);

#pragma unroll
            for (int mb = 0; mb < 4; mb++) {
                const int r0 = m0 + warp_m * 64 + mb * 16 + (lane >> 2);
                float* p0 = out + (size_t)r0 * OUT_F;
                float* p1 = p0 + (size_t)8 * OUT_F;
#pragma unroll
                for (int nf = 0; nf < 8; nf++) {
                    float2 v0, v1;
                    v0.x = acc[mb][nf][0] + bb[nf].x;
                    v0.y = acc[mb][nf][1] + bb[nf].y;
                    v1.x = acc[mb][nf][2] + bb[nf].x;
                    v1.y = acc[mb][nf][3] + bb[nf].y;
                    *reinterpret_cast<float2*>(p0 + col + nf * 8) = v0;
                    *reinterpret_cast<float2*>(p1 + col + nf * 8) = v1;
                    acc[mb][nf][0] = 0.0f; acc[mb][nf][1] = 0.0f;
                    acc[mb][nf][2] = 0.0f; acc[mb][nf][3] = 0.0f;
                }
            }
        } else {
            // K-split piece: accumulate into pre-biased output
#pragma unroll
            for (int mb = 0; mb < 4; mb++) {
                const int r0 = m0 + warp_m * 64 + mb * 16 + (lane >> 2);
                float* p0 = out + (size_t)r0 * OUT_F;
                float* p1 = p0 + (size_t)8 * OUT_F;
#pragma unroll
                for (int nf = 0; nf < 8; nf++) {
                    REDADD(p0 + col + nf * 8,     acc[mb][nf][0]);
                    REDADD(p0 + col + nf * 8 + 1, acc[mb][nf][1]);
                    REDADD(p1 + col + nf * 8,     acc[mb][nf][2]);
                    REDADD(p1 + col + nf * 8 + 1, acc[mb][nf][3]);
                    acc[mb][nf][0] = 0.0f; acc[mb][nf][1] = 0.0f;
                    acc[mb][nf][2] = 0.0f; acc[mb][nf][3] = 0.0f;
                }
            }
        }
    }
}

// ---------------- launch ----------------
extern "C" void kernel_launch(void* const* d_in, const int* in_sizes, int n_in,
                              void* d_out, int out_size) {
    const float* x     = (const float*)d_in[0];
    const int*   Wq    = (const int*)  d_in[1];
    const float* scale = (const float*)d_in[2];
    const float* zero  = (const float*)d_in[3];
    const float* bias  = (const float*)d_in[4];
    float* out = (float*)d_out;

    int sm_count = 148;
    cudaDeviceGetAttribute(&sm_count, cudaDevAttrMultiProcessorCount, 0);
    int nctas = 2 * sm_count;
    int S = TOTAL_TILES - FULL_PER_CTA * nctas;   // tiles to K-split (88 on 148 SMs)
    if (S < 0) S = 0;
    int F = TOTAL_TILES - S;

    prep_kernel<<<PREP_X_BLOCKS + PREP_W_BLOCKS + S * 16, 256>>>(
        x, Wq, scale, zero, out, bias, F);

    cudaFuncSetAttribute(gemm_kernel, cudaFuncAttributeMaxDynamicSharedMemorySize, SMEM_DYN);
    gemm_kernel<<<nctas, 128, SMEM_DYN>>>(out, bias, F, nctas, 4 * S);
}